// round 15
// baseline (speedup 1.0000x reference)
#include <cuda_runtime.h>

// Shapes fixed by reference setup_inputs
#define NTOK   16384      // B*T
#define DDIM   2048
#define NEXP   16
#define TOK_W  4          // tokens per warp (one group per warp)
#define NGRP   (NTOK / TOK_W)          // 4096 groups
#define GRID_MAIN 148
#define BLOCK_MAIN 896    // 28 warps -> 4144 warps for 4096 groups
#define WARPS_CTA 28
#define NHC    32         // half-chunks of 64 d
#define STAGES 3
#define STG_FLOATS 256    // 4 tok * 64 d floats = 1KB per stage

#define W2_U64      (NEXP * DDIM / 2)              // 16384 u64 = 128KB
#define XSTG_FLOATS (WARPS_CTA * STAGES * STG_FLOATS)

__device__ float g_zp[GRID_MAIN];     // per-CTA z-loss partials (deterministic)
__device__ unsigned int g_ctr;        // last-CTA ticket (reset each launch)

typedef unsigned long long u64;

__device__ __forceinline__ float fnoise(float x) {
    return copysignf(sqrtf(fabsf(x)), x);
}
__device__ __forceinline__ void ffma2(u64 &d, u64 a, u64 b) {
    asm("fma.rn.f32x2 %0, %1, %2, %0;" : "+l"(d) : "l"(a), "l"(b));
}
__device__ __forceinline__ u64 addx2(u64 a, u64 b) {
    u64 r; asm("add.rn.f32x2 %0, %1, %2;" : "=l"(r) : "l"(a), "l"(b)); return r;
}
__device__ __forceinline__ u64 pack2(float lo, float hi) {
    u64 r; asm("mov.b64 %0, {%1, %2};" : "=l"(r) : "f"(lo), "f"(hi)); return r;
}
__device__ __forceinline__ float2 unpack64(u64 v) {
    float2 r; asm("mov.b64 {%0, %1}, %2;" : "=f"(r.x), "=f"(r.y) : "l"(v)); return r;
}
__device__ __forceinline__ unsigned smem_u32(const void* p) {
    return (unsigned)__cvta_generic_to_shared(p);
}
__device__ __forceinline__ void cp16(unsigned dst, const float* src) {
    asm volatile("cp.async.cg.shared.global [%0], [%1], 16;"
                 :: "r"(dst), "l"(src) : "memory");
}
__device__ __forceinline__ void cp_commit() {
    asm volatile("cp.async.commit_group;" ::: "memory");
}
__device__ __forceinline__ void cp_wait2() {
    asm volatile("cp.async.wait_group 2;" ::: "memory");
}
__device__ __forceinline__ void cp_wait0() {
    asm volatile("cp.async.wait_group 0;" ::: "memory");
}

// ---------------------------------------------------------------------------
// High-occupancy variant of the R14 quarter-split kernel:
//   28 warps/CTA (896 thr), 4 tokens/warp, one group per warp.
//   acc[4 tok][4 exp] packed f32x2 (even-d, odd-d sums) = 32 regs -> fits
//   the 73-reg cap at 896 threads.
//   Warp = 4 quarters (8 lanes); quarter q owns experts 4q..4q+3.
//   SMEM w (d-pair packed): u64 idx = wi*256 + el*64 + lane*2 + k
//   -> one conflict-free LDS.128 per e_local per 32-d window.
//   x staged per warp via depth-3 cp.async (64-d half-chunks, 1KB stages);
//   x read is 4-way same-address broadcast across quarters.
//   Epilogue (lanes 0-15): cross-quarter exchange through retired stage,
//   per-lane top-2/softmax, fused last-CTA z-loss.
// ---------------------------------------------------------------------------
__global__ void __launch_bounds__(BLOCK_MAIN, 1)
router_kernel(const float* __restrict__ x,
              const float* __restrict__ w,  const float* __restrict__ sw,
              const float* __restrict__ b,  const float* __restrict__ sb,
              const float* __restrict__ ei, const float* __restrict__ eo,
              float* __restrict__ out) {
    extern __shared__ __align__(16) char smem_raw[];
    u64*   w2_s   = (u64*)smem_raw;                                  // 128KB
    float* xstage = (float*)(w2_s + W2_U64);                         // 84KB
    float* fi_s   = xstage + XSTG_FLOATS;                            // 2048
    float* fo_s   = fi_s + DDIM;                                     // 16
    float* b_s    = fo_s + NEXP;                                     // 16
    float* z_s    = b_s + NEXP;                                      // 28

    // --- noise factors ---
    for (int i = threadIdx.x; i < DDIM; i += BLOCK_MAIN) fi_s[i] = fnoise(ei[i]);
    if (threadIdx.x < NEXP) {
        float fo = fnoise(eo[threadIdx.x]);
        fo_s[threadIdx.x] = fo;
        b_s[threadIdx.x] = b[threadIdx.x] + sb[threadIdx.x] * fo;
    }
    __syncthreads();

    // --- noisy weights into window/e_local/lane layout (d-pair packed) ---
    for (int it = threadIdx.x; it < NEXP * (DDIM / 2); it += BLOCK_MAIN) {
        int e = it >> 10;              // expert
        int d = (it & 1023) * 2;       // even d
        float2 wv = *(const float2*)(w  + e * DDIM + d);
        float2 sv = *(const float2*)(sw + e * DDIM + d);
        float2 fi = *(const float2*)(fi_s + d);
        float fo = fo_s[e];
        float a0 = wv.x + sv.x * fo * fi.x;
        float a1 = wv.y + sv.y * fo * fi.y;
        int wi = d >> 5, el = e & 3, q = e >> 2;
        int j = (d >> 2) & 7, k = (d >> 1) & 1;
        w2_s[wi * 256 + el * 64 + (q * 8 + j) * 2 + k] = pack2(a0, a1);
    }
    __syncthreads();

    const int lane = threadIdx.x & 31;
    const int wid  = threadIdx.x >> 5;
    const int gw   = blockIdx.x * WARPS_CTA + wid;   // group id == warp id
    const int j8   = lane & 7;                       // d-slot within window
    const int q4   = lane >> 3;                      // quarter (expert group)

    float* warp_stg = xstage + wid * (STAGES * STG_FLOATS);
    float* idx_out  = out + (size_t)NTOK * NEXP;

    if (gw < NGRP) {
        const int t0 = gw * TOK_W;
        const float* xg = x + (size_t)t0 * DDIM;
        unsigned stg_u32 = smem_u32(warp_stg);

        // prime 3 stages with half-chunks 0..2
        // stage holds 64 16B-slots: slot = t*16 + s4; each lane covers 2 slots
        #pragma unroll
        for (int s = 0; s < STAGES; s++) {
            #pragma unroll
            for (int tp = 0; tp < 2; tp++) {
                int slot = tp * 32 + lane;
                int t = slot >> 4, s4 = slot & 15;
                cp16(stg_u32 + s * 1024 + slot * 16,
                     xg + t * DDIM + s * 64 + s4 * 4);
            }
            cp_commit();
        }

        u64 acc[TOK_W][4];
        #pragma unroll
        for (int t = 0; t < TOK_W; t++)
            #pragma unroll
            for (int el = 0; el < 4; el++) acc[t][el] = 0ULL;

        int stage = 0;
        #pragma unroll 1
        for (int hc = 0; hc < NHC; hc++) {
            cp_wait2();   // half-chunk hc resident

            #pragma unroll
            for (int sub = 0; sub < 2; sub++) {
                const int wi = hc * 2 + sub;
                // hoist w for this 32-d window: 4 conflict-free LDS.128
                const u64* wb = w2_s + wi * 256 + lane * 2;
                u64 wv[4][2];
                #pragma unroll
                for (int el = 0; el < 4; el++) {
                    ulonglong2 u = *(const ulonglong2*)(wb + el * 64);
                    wv[el][0] = u.x;   // (w[d],   w[d+1])
                    wv[el][1] = u.y;   // (w[d+2], w[d+3])
                }
                const float* xs = warp_stg + stage * STG_FLOATS + sub * 32 + j8 * 4;
                #pragma unroll
                for (int t = 0; t < TOK_W; t++) {
                    ulonglong2 xu = *(const ulonglong2*)(xs + t * 64);
                    #pragma unroll
                    for (int el = 0; el < 4; el++) {
                        ffma2(acc[t][el], xu.x, wv[el][0]);
                        ffma2(acc[t][el], xu.y, wv[el][1]);
                    }
                }
            }

            // refill this stage with half-chunk hc+3
            if (hc < NHC - STAGES) {
                #pragma unroll
                for (int tp = 0; tp < 2; tp++) {
                    int slot = tp * 32 + lane;
                    int t = slot >> 4, s4 = slot & 15;
                    cp16(stg_u32 + stage * 1024 + slot * 16,
                         xg + t * DDIM + (hc + 3) * 64 + s4 * 4);
                }
            }
            cp_commit();   // uniform commit keeps wait_group algebra exact
            stage = (stage == STAGES - 1) ? 0 : stage + 1;
        }
        cp_wait0();   // drain before reusing the stage as scratch

        // butterfly within each 8-lane quarter, then even+odd horizontal add
        float fs[TOK_W][4];
        #pragma unroll
        for (int t = 0; t < TOK_W; t++)
            #pragma unroll
            for (int el = 0; el < 4; el++) {
                u64 s = acc[t][el];
                s = addx2(s, __shfl_xor_sync(0xffffffffu, s, 4));
                s = addx2(s, __shfl_xor_sync(0xffffffffu, s, 2));
                s = addx2(s, __shfl_xor_sync(0xffffffffu, s, 1));
                float2 qv = unpack64(s);
                fs[t][el] = qv.x + qv.y;
            }

        // cross-quarter exchange through this warp's retired stage memory
        float* red = warp_stg;           // 64 floats used
        if (j8 == 0) {
            #pragma unroll
            for (int t = 0; t < TOK_W; t++)
                *(float4*)(red + t * 16 + q4 * 4) =
                    make_float4(fs[t][0], fs[t][1], fs[t][2], fs[t][3]);
        }
        __syncwarp();

        float zl = 0.0f;
        if (lane < 16) {
            const int town = lane >> 2;      // this lane's token (0..3)
            const int qq   = lane & 3;       // this lane's 4-expert slice
            float v[NEXP];
            #pragma unroll
            for (int g2 = 0; g2 < 4; g2++) {
                float4 u = *(const float4*)(red + town * 16 + g2 * 4);
                v[g2 * 4 + 0] = u.x;
                v[g2 * 4 + 1] = u.y;
                v[g2 * 4 + 2] = u.z;
                v[g2 * 4 + 3] = u.w;
            }

            // top-2 + softmax + z for this lane's token
            float m1 = -1e30f, m2 = -1e30f;
            int i1 = 0, i2 = 0;
            #pragma unroll
            for (int e = 0; e < NEXP; e++) {
                float le = v[e] + b_s[e];
                if (le > m1)      { m2 = m1; i2 = i1; m1 = le; i1 = e; }
                else if (le > m2) { m2 = le; i2 = e; }
            }
            float ez = __expf(m2 - m1);
            float rz = 1.0f / (1.0f + ez);
            float p1 = rz, p2 = ez * rz;

            const int tok = t0 + town;
            const int e0 = qq * 4;
            float4 o4;
            o4.x = (e0 + 0 == i1) ? p1 : ((e0 + 0 == i2) ? p2 : 0.0f);
            o4.y = (e0 + 1 == i1) ? p1 : ((e0 + 1 == i2) ? p2 : 0.0f);
            o4.z = (e0 + 2 == i1) ? p1 : ((e0 + 2 == i2) ? p2 : 0.0f);
            o4.w = (e0 + 3 == i1) ? p1 : ((e0 + 3 == i2) ? p2 : 0.0f);
            *(float4*)(out + (size_t)tok * NEXP + e0) = o4;
            if (qq == 0)
                *(float2*)(idx_out + (size_t)tok * 2) =
                    make_float2((float)i1, (float)i2);

            float lse = m1 + log1pf(ez);
            zl = (qq == 0) ? lse * lse : 0.0f;
        }
        #pragma unroll
        for (int k = 16; k > 0; k >>= 1)
            zl += __shfl_xor_sync(0xffffffffu, zl, k);
        if (lane == 0) z_s[wid] = zl;
    } else {
        if (lane == 0) z_s[wid] = 0.0f;
    }

    // --- fused z-loss reduction: CTA partial, then last CTA finishes ---
    __syncthreads();
    __shared__ unsigned int s_last;
    if (threadIdx.x == 0) {
        float a = 0.0f;
        #pragma unroll
        for (int i = 0; i < WARPS_CTA; i++) a += z_s[i];
        g_zp[blockIdx.x] = a;
        __threadfence();
        unsigned int ticket = atomicAdd(&g_ctr, 1u);
        s_last = (ticket == GRID_MAIN - 1) ? 1u : 0u;
    }
    __syncthreads();
    if (s_last && wid == 0) {
        float a = 0.0f;
        for (int i = lane; i < GRID_MAIN; i += 32) a += __ldcg(&g_zp[i]);
        #pragma unroll
        for (int k = 16; k > 0; k >>= 1)
            a += __shfl_xor_sync(0xffffffffu, a, k);
        if (lane == 0) {
            out[(size_t)NTOK * NEXP + (size_t)NTOK * 2] = a * (1.0f / (float)NTOK);
            g_ctr = 0;   // reset for next launch / graph replay
        }
    }
}

// ---------------------------------------------------------------------------
extern "C" void kernel_launch(void* const* d_in, const int* in_sizes, int n_in,
                              void* d_out, int out_size) {
    const float* x  = (const float*)d_in[0];  // mh_output [4,4096,2048]
    const float* w  = (const float*)d_in[1];  // weight [16,2048]
    const float* sw = (const float*)d_in[2];  // sigma_weight
    const float* b  = (const float*)d_in[3];  // bias [16]
    const float* sb = (const float*)d_in[4];  // sigma_bias
    const float* ei = (const float*)d_in[5];  // eps_in [2048]
    const float* eo = (const float*)d_in[6];  // eps_out [16]
    float* out = (float*)d_out;

    const size_t smem_bytes = (size_t)W2_U64 * 8
                            + (size_t)XSTG_FLOATS * 4
                            + (size_t)(DDIM + 2 * NEXP + WARPS_CTA) * sizeof(float)
                            + 64;
    cudaFuncSetAttribute(router_kernel,
                         cudaFuncAttributeMaxDynamicSharedMemorySize,
                         (int)smem_bytes);
    router_kernel<<<GRID_MAIN, BLOCK_MAIN, smem_bytes>>>(x, w, sw, b, sb, ei, eo, out);
}

// round 16
// speedup vs baseline: 1.0452x; 1.0452x over previous
#include <cuda_runtime.h>

// Shapes fixed by reference setup_inputs
#define NTOK   16384      // B*T
#define DDIM   2048
#define NEXP   16
#define TOK_W  8          // tokens per group
#define NGRP   (NTOK / TOK_W)          // 2048 groups
#define NASSIGN (NGRP * 2)             // 4096 warp assignments (group x d-half)
#define GRID_MAIN 148
#define BLOCK_MAIN 896
#define WARPS_CTA 28
#define NWIN   32         // 32-d windows per d-half
#define STAGES 3
#define STG_FLOATS 256    // 8 tok * 32 d = 1KB per stage

#define W4_FLOATS   (NEXP * DDIM)                  // 32768 floats = 128KB
#define XSTG_FLOATS (WARPS_CTA * STAGES * STG_FLOATS)   // 21504 floats = 84KB

__device__ float g_zp[GRID_MAIN];     // per-CTA z-loss partials (deterministic)
__device__ unsigned int g_ctr;        // last-CTA ticket (reset each launch)

__device__ __forceinline__ float fnoise(float x) {
    return copysignf(sqrtf(fabsf(x)), x);
}
__device__ __forceinline__ unsigned smem_u32(const void* p) {
    return (unsigned)__cvta_generic_to_shared(p);
}
__device__ __forceinline__ void cp16(unsigned dst, const float* src) {
    asm volatile("cp.async.cg.shared.global [%0], [%1], 16;"
                 :: "r"(dst), "l"(src) : "memory");
}
__device__ __forceinline__ void cp_commit() {
    asm volatile("cp.async.commit_group;" ::: "memory");
}
__device__ __forceinline__ void cp_wait2() {
    asm volatile("cp.async.wait_group 2;" ::: "memory");
}
__device__ __forceinline__ void cp_wait0() {
    asm volatile("cp.async.wait_group 0;" ::: "memory");
}

// ---------------------------------------------------------------------------
// D-split warp-pair kernel: breaks the occupancy<->w-traffic lockstep.
//   Assignment a = blockIdx*28 + wid (a < 4096): group g = a>>1 (8 tokens),
//   d-half = a&1 (1024 d).  Partner warp = wid^1, SAME CTA.
//   28 warps/CTA (R15 occupancy) with R14's total w-LDS traffic.
//   fp32 accumulators acc[8 tok][4 exp] = 32 regs -> fits 73-reg cap, no
//   packing MOVs anywhere in the mainloop.
//   Warp = 4 quarters (8 lanes); quarter q owns experts 4q..4q+3; lane j8
//   owns d = win*32 + j8*4 .. +3.
//   SMEM w plain floats: w4_s[win*512 + el*128 + lane*4 + dm]
//     -> per (window, el): ONE conflict-free LDS.128 per lane.
//   x staged per warp via depth-3 cp.async, 32-d windows, 1KB stages.
//   Halves combined through retired x-stages + one __syncthreads; even warp
//   of each pair does top-2/softmax/z epilogue for all 8 tokens.
// ---------------------------------------------------------------------------
__global__ void __launch_bounds__(BLOCK_MAIN, 1)
router_kernel(const float* __restrict__ x,
              const float* __restrict__ w,  const float* __restrict__ sw,
              const float* __restrict__ b,  const float* __restrict__ sb,
              const float* __restrict__ ei, const float* __restrict__ eo,
              float* __restrict__ out) {
    extern __shared__ __align__(16) float smem_raw[];
    float* w4_s   = smem_raw;                        // 128KB
    float* xstage = w4_s + W4_FLOATS;                // 84KB
    float* fi_s   = xstage + XSTG_FLOATS;            // 2048
    float* fo_s   = fi_s + DDIM;                     // 16
    float* b_s    = fo_s + NEXP;                     // 16
    float* z_s    = b_s + NEXP;                      // 28

    // --- noise factors ---
    for (int i = threadIdx.x; i < DDIM; i += BLOCK_MAIN) fi_s[i] = fnoise(ei[i]);
    if (threadIdx.x < NEXP) {
        float fo = fnoise(eo[threadIdx.x]);
        fo_s[threadIdx.x] = fo;
        b_s[threadIdx.x] = b[threadIdx.x] + sb[threadIdx.x] * fo;
    }
    __syncthreads();

    // --- noisy weights into [win][el][lane][dm] float layout ---
    // idx = win*512 + el*128 + ((e>>2)*8 + ((d>>2)&7))*4 + (d&3)
    for (int c4 = threadIdx.x; c4 < (NEXP * DDIM) / 4; c4 += BLOCK_MAIN) {
        int e = c4 >> 9;               // expert
        int d = (c4 & 511) * 4;        // d multiple of 4
        float4 wv = *(const float4*)(w  + e * DDIM + d);
        float4 sv = *(const float4*)(sw + e * DDIM + d);
        float4 fi = *(const float4*)(fi_s + d);
        float fo = fo_s[e];
        float4 r;
        r.x = wv.x + sv.x * fo * fi.x;
        r.y = wv.y + sv.y * fo * fi.y;
        r.z = wv.z + sv.z * fo * fi.z;
        r.w = wv.w + sv.w * fo * fi.w;
        int win = d >> 5, el = e & 3;
        int lane = (e >> 2) * 8 + ((d >> 2) & 7);
        *(float4*)(w4_s + win * 512 + el * 128 + lane * 4) = r;
    }
    __syncthreads();

    const int lane = threadIdx.x & 31;
    const int wid  = threadIdx.x >> 5;
    const int a    = blockIdx.x * WARPS_CTA + wid;   // assignment id
    const int j8   = lane & 7;                       // d-slot within window
    const int q4   = lane >> 3;                      // quarter (expert group)
    const bool act = (a < NASSIGN);
    const int g    = a >> 1;                         // token group
    const int half = a & 1;                          // d half

    float* warp_stg = xstage + wid * (STAGES * STG_FLOATS);

    float fs[TOK_W][4];

    if (act) {
        const int t0 = g * TOK_W;
        const float* xg = x + (size_t)t0 * DDIM + half * 1024;
        unsigned stg_u32 = smem_u32(warp_stg);

        // prime 3 stages with windows 0..2  (stage: 64 16B-slots, slot=t*8+s4)
        #pragma unroll
        for (int s = 0; s < STAGES; s++) {
            #pragma unroll
            for (int tp = 0; tp < 2; tp++) {
                int slot = tp * 32 + lane;
                int t = slot >> 3, s4 = slot & 7;
                cp16(stg_u32 + s * 1024 + slot * 16,
                     xg + t * DDIM + s * 32 + s4 * 4);
            }
            cp_commit();
        }

        float acc[TOK_W][4];
        #pragma unroll
        for (int t = 0; t < TOK_W; t++)
            #pragma unroll
            for (int el = 0; el < 4; el++) acc[t][el] = 0.0f;

        int stage = 0;
        #pragma unroll 1
        for (int wi = 0; wi < NWIN; wi++) {
            cp_wait2();   // window wi resident

            // hoist w for this window: 4 conflict-free LDS.128
            const float* wb = w4_s + (half * NWIN + wi) * 512 + lane * 4;
            float4 wv0 = *(const float4*)(wb + 0 * 128);
            float4 wv1 = *(const float4*)(wb + 1 * 128);
            float4 wv2 = *(const float4*)(wb + 2 * 128);
            float4 wv3 = *(const float4*)(wb + 3 * 128);

            const float* xs = warp_stg + stage * STG_FLOATS + j8 * 4;
            #pragma unroll
            for (int t = 0; t < TOK_W; t++) {
                float4 xv = *(const float4*)(xs + t * 32);
                acc[t][0] += xv.x * wv0.x + xv.y * wv0.y + xv.z * wv0.z + xv.w * wv0.w;
                acc[t][1] += xv.x * wv1.x + xv.y * wv1.y + xv.z * wv1.z + xv.w * wv1.w;
                acc[t][2] += xv.x * wv2.x + xv.y * wv2.y + xv.z * wv2.z + xv.w * wv2.w;
                acc[t][3] += xv.x * wv3.x + xv.y * wv3.y + xv.z * wv3.z + xv.w * wv3.w;
            }

            // refill this stage with window wi+3
            if (wi < NWIN - STAGES) {
                #pragma unroll
                for (int tp = 0; tp < 2; tp++) {
                    int slot = tp * 32 + lane;
                    int t = slot >> 3, s4 = slot & 7;
                    cp16(stg_u32 + stage * 1024 + slot * 16,
                         xg + t * DDIM + (wi + 3) * 32 + s4 * 4);
                }
            }
            cp_commit();   // uniform commit keeps wait_group algebra exact
            stage = (stage == STAGES - 1) ? 0 : stage + 1;
        }
        cp_wait0();   // drain before reusing own stage as scratch

        // butterfly over the 8 j8-lanes within each quarter
        #pragma unroll
        for (int t = 0; t < TOK_W; t++)
            #pragma unroll
            for (int el = 0; el < 4; el++) {
                float s = acc[t][el];
                s += __shfl_xor_sync(0xffffffffu, s, 4);
                s += __shfl_xor_sync(0xffffffffu, s, 2);
                s += __shfl_xor_sync(0xffffffffu, s, 1);
                fs[t][el] = s;
            }

        // publish this half's 8x16 partial logits into own retired stage
        // red[t*16 + q4*4 + el]
        if (j8 == 0) {
            #pragma unroll
            for (int t = 0; t < TOK_W; t++)
                *(float4*)(warp_stg + t * 16 + q4 * 4) =
                    make_float4(fs[t][0], fs[t][1], fs[t][2], fs[t][3]);
        }
    }

    __syncthreads();   // all halves published

    float zl = 0.0f;
    if (act && half == 0) {
        // combine with partner (wid^1 = wid+1, same CTA) and run epilogue
        const float* r0 = warp_stg;                            // own (half 0)
        const float* r1 = xstage + (wid + 1) * (STAGES * STG_FLOATS); // half 1

        const int town = lane >> 2;      // this lane's token (0..7)
        const int qq   = lane & 3;       // this lane's 4-expert output slice
        const int t0   = g * TOK_W;
        float* idx_out = out + (size_t)NTOK * NEXP;

        float v[NEXP];
        #pragma unroll
        for (int g2 = 0; g2 < 4; g2++) {
            float4 u0 = *(const float4*)(r0 + town * 16 + g2 * 4);
            float4 u1 = *(const float4*)(r1 + town * 16 + g2 * 4);
            v[g2 * 4 + 0] = u0.x + u1.x;
            v[g2 * 4 + 1] = u0.y + u1.y;
            v[g2 * 4 + 2] = u0.z + u1.z;
            v[g2 * 4 + 3] = u0.w + u1.w;
        }

        float m1 = -1e30f, m2 = -1e30f;
        int i1 = 0, i2 = 0;
        #pragma unroll
        for (int e = 0; e < NEXP; e++) {
            float le = v[e] + b_s[e];
            if (le > m1)      { m2 = m1; i2 = i1; m1 = le; i1 = e; }
            else if (le > m2) { m2 = le; i2 = e; }
        }
        float ez = __expf(m2 - m1);
        float rz = 1.0f / (1.0f + ez);
        float p1 = rz, p2 = ez * rz;

        const int tok = t0 + town;
        const int e0 = qq * 4;
        float4 o4;
        o4.x = (e0 + 0 == i1) ? p1 : ((e0 + 0 == i2) ? p2 : 0.0f);
        o4.y = (e0 + 1 == i1) ? p1 : ((e0 + 1 == i2) ? p2 : 0.0f);
        o4.z = (e0 + 2 == i1) ? p1 : ((e0 + 2 == i2) ? p2 : 0.0f);
        o4.w = (e0 + 3 == i1) ? p1 : ((e0 + 3 == i2) ? p2 : 0.0f);
        *(float4*)(out + (size_t)tok * NEXP + e0) = o4;
        if (qq == 0)
            *(float2*)(idx_out + (size_t)tok * 2) =
                make_float2((float)i1, (float)i2);

        float lse = m1 + log1pf(ez);
        zl = (qq == 0) ? lse * lse : 0.0f;
    }
    // warp-reduce z (inactive / odd warps contribute 0)
    #pragma unroll
    for (int k = 16; k > 0; k >>= 1)
        zl += __shfl_xor_sync(0xffffffffu, zl, k);
    if (lane == 0) z_s[wid] = zl;

    // --- fused z-loss reduction: CTA partial, then last CTA finishes ---
    __syncthreads();
    __shared__ unsigned int s_last;
    if (threadIdx.x == 0) {
        float acc_z = 0.0f;
        #pragma unroll
        for (int i = 0; i < WARPS_CTA; i++) acc_z += z_s[i];
        g_zp[blockIdx.x] = acc_z;
        __threadfence();
        unsigned int ticket = atomicAdd(&g_ctr, 1u);
        s_last = (ticket == GRID_MAIN - 1) ? 1u : 0u;
    }
    __syncthreads();
    if (s_last && wid == 0) {
        float acc_z = 0.0f;
        for (int i = lane; i < GRID_MAIN; i += 32) acc_z += __ldcg(&g_zp[i]);
        #pragma unroll
        for (int k = 16; k > 0; k >>= 1)
            acc_z += __shfl_xor_sync(0xffffffffu, acc_z, k);
        if (lane == 0) {
            out[(size_t)NTOK * NEXP + (size_t)NTOK * 2] = acc_z * (1.0f / (float)NTOK);
            g_ctr = 0;   // reset for next launch / graph replay
        }
    }
}

// ---------------------------------------------------------------------------
extern "C" void kernel_launch(void* const* d_in, const int* in_sizes, int n_in,
                              void* d_out, int out_size) {
    const float* x  = (const float*)d_in[0];  // mh_output [4,4096,2048]
    const float* w  = (const float*)d_in[1];  // weight [16,2048]
    const float* sw = (const float*)d_in[2];  // sigma_weight
    const float* b  = (const float*)d_in[3];  // bias [16]
    const float* sb = (const float*)d_in[4];  // sigma_bias
    const float* ei = (const float*)d_in[5];  // eps_in [2048]
    const float* eo = (const float*)d_in[6];  // eps_out [16]
    float* out = (float*)d_out;

    const size_t smem_bytes = (size_t)(W4_FLOATS + XSTG_FLOATS
                            + DDIM + 2 * NEXP + WARPS_CTA) * sizeof(float)
                            + 64;
    cudaFuncSetAttribute(router_kernel,
                         cudaFuncAttributeMaxDynamicSharedMemorySize,
                         (int)smem_bytes);
    router_kernel<<<GRID_MAIN, BLOCK_MAIN, smem_bytes>>>(x, w, sw, b, sb, ei, eo, out);
}